// round 11
// baseline (speedup 1.0000x reference)
#include <cuda_runtime.h>
#include <cuda_fp16.h>
#include <cstdint>

// y[b,o] = sum_j relu(w[o,j]*x_aug[b,j])
//        = x.(0.5w) + |x|.|0.5w| + relu(w[o,256])   (0.5 folded into W, exact)
// fp16 mma.sync m16n8k16; abs on packed fp16x2 regs; both terms -> same fp32 C.
// Monolithic: full 128x256 A and B tiles resident in smem, ONE barrier,
// then 16 uninterrupted kk MMA iterations (no u-loop, no double buffer).

#define BM 128
#define BN 128
#define KDIM 256
#define WSTRIDE 257
#define NDIM 256

#define TILE_BYTES 16384          // 128 rows x 64 fp16 (128B rows), per k-chunk
#define B_OFF (4 * TILE_BYTES)    // A chunks 0-3, then B chunks 0-3
#define DYN_BYTES (8 * TILE_BYTES + 1024)

__device__ __forceinline__ uint32_t swz(uint32_t o) { return o ^ ((o >> 3) & 0x70u); }

__device__ __forceinline__ uint32_t smem_u32(const void* p) {
    uint32_t a;
    asm("{ .reg .u64 t; cvta.to.shared.u64 t, %1; cvt.u32.u64 %0, t; }" : "=r"(a) : "l"(p));
    return a;
}

#define LDSM4(r0, r1, r2, r3, addr) \
    asm volatile("ldmatrix.sync.aligned.m8n8.x4.shared.b16 {%0,%1,%2,%3}, [%4];" \
                 : "=r"(r0), "=r"(r1), "=r"(r2), "=r"(r3) : "r"(addr))
#define MMA16816(c, a, b0, b1) \
    asm volatile("mma.sync.aligned.m16n8k16.row.col.f32.f16.f16.f32 " \
                 "{%0,%1,%2,%3}, {%4,%5,%6,%7}, {%8,%9}, {%0,%1,%2,%3};" \
                 : "+f"((c)[0]), "+f"((c)[1]), "+f"((c)[2]), "+f"((c)[3]) \
                 : "r"((a)[0]), "r"((a)[1]), "r"((a)[2]), "r"((a)[3]), "r"(b0), "r"(b1))

__device__ __forceinline__ uint32_t pack_h2(float a, float b) {
    __half2 h = __floats2half2_rn(a, b);
    return *reinterpret_cast<uint32_t*>(&h);
}

__global__ __launch_bounds__(512, 1)
void skan_mma_kernel(const float* __restrict__ x,
                     const float* __restrict__ w,
                     float* __restrict__ out)
{
    extern __shared__ char dynraw[];
    __shared__ float bias_s[BN];

    char* sb = (char*)(((uintptr_t)dynraw + 1023) & ~(uintptr_t)1023);
    const uint32_t sb_u = smem_u32(sb);

    const int tid = threadIdx.x;
    const int lane = tid & 31;
    const int wid = tid >> 5;
    const int bm = blockIdx.y * BM;
    const int bn = blockIdx.x * BN;
    const int wm = wid & 3;     // warp row (4 x 32)
    const int wn = wid >> 2;    // warp col (4 x 32)

    if (tid < BN)
        bias_s[tid] = fmaxf(__ldg(w + (size_t)(bn + tid) * WSTRIDE + 256), 0.0f);

    // ---- fill: whole A (x, 128x256) and B (0.5*w, 128x256) tiles, once ----
    // thread -> row = tid>>2 (0..127), k-chunk = tid&3 (64 cols)
    {
        const int row = tid >> 2;
        const int ch = tid & 3;

        // A: x rows are 256-float (16B-aligned) -> float4 loads
        const float* xp = x + (size_t)(bm + row) * KDIM + ch * 64;
        char* at = sb + ch * TILE_BYTES;
        const uint32_t ob = (uint32_t)(row * 128);
#pragma unroll
        for (int g = 0; g < 4; g++) {
            const float4 v0 = *reinterpret_cast<const float4*>(xp + 16 * g);
            const float4 v1 = *reinterpret_cast<const float4*>(xp + 16 * g + 4);
            const float4 v2 = *reinterpret_cast<const float4*>(xp + 16 * g + 8);
            const float4 v3 = *reinterpret_cast<const float4*>(xp + 16 * g + 12);
            uint4 s0, s1;
            s0.x = pack_h2(v0.x, v0.y);  s0.y = pack_h2(v0.z, v0.w);
            s0.z = pack_h2(v1.x, v1.y);  s0.w = pack_h2(v1.z, v1.w);
            s1.x = pack_h2(v2.x, v2.y);  s1.y = pack_h2(v2.z, v2.w);
            s1.z = pack_h2(v3.x, v3.y);  s1.w = pack_h2(v3.z, v3.w);
            *reinterpret_cast<uint4*>(at + swz(ob + 32 * g))      = s0;
            *reinterpret_cast<uint4*>(at + swz(ob + 32 * g + 16)) = s1;
        }

        // B: w rows are 257-float (unaligned) -> scalar loads, 0.5 folded in
        const float* wp = w + (size_t)(bn + row) * WSTRIDE + ch * 64;
        char* bt = sb + B_OFF + ch * TILE_BYTES;
#pragma unroll
        for (int g = 0; g < 8; g++) {
            const float* q = wp + 8 * g;
            uint4 st;
            st.x = pack_h2(0.5f * __ldg(q + 0), 0.5f * __ldg(q + 1));
            st.y = pack_h2(0.5f * __ldg(q + 2), 0.5f * __ldg(q + 3));
            st.z = pack_h2(0.5f * __ldg(q + 4), 0.5f * __ldg(q + 5));
            st.w = pack_h2(0.5f * __ldg(q + 6), 0.5f * __ldg(q + 7));
            *reinterpret_cast<uint4*>(bt + swz(ob + 16 * g)) = st;
        }
    }
    __syncthreads();            // the ONE barrier

    float acc[2][4][4];
#pragma unroll
    for (int mt = 0; mt < 2; mt++)
#pragma unroll
        for (int nt = 0; nt < 4; nt++)
#pragma unroll
            for (int q = 0; q < 4; q++) acc[mt][nt][q] = 0.0f;

    // ---- compute: 16 kk iterations, no barriers ----
#pragma unroll
    for (int kk = 0; kk < 16; kk++) {
        const int ch = kk >> 2;
        const int col = (kk & 3) * 16 + (lane >> 4) * 8;
        const uint32_t Abase = sb_u + ch * TILE_BYTES;
        const uint32_t Bbase = sb_u + B_OFF + ch * TILE_BYTES;

        uint32_t A[2][4], Aa[2][4];
#pragma unroll
        for (int mt = 0; mt < 2; mt++) {
            const int row = wm * 32 + mt * 16 + (lane & 15);
            const uint32_t addr = Abase + swz((uint32_t)(row * 128 + col * 2));
            LDSM4(A[mt][0], A[mt][1], A[mt][2], A[mt][3], addr);
        }
        // B: non-trans ldmatrix on [n][k] tile.
        // matrices: 0 = n0:8 k-lo, 1 = n8:16 k-lo, 2 = n0:8 k-hi, 3 = n8:16 k-hi
        uint32_t B2[2][4], Ba[2][4];
#pragma unroll
        for (int np = 0; np < 2; np++) {
            const int nrow = wn * 32 + np * 16 + (lane & 15);
            const uint32_t addr = Bbase + swz((uint32_t)(nrow * 128 + col * 2));
            LDSM4(B2[np][0], B2[np][1], B2[np][2], B2[np][3], addr);
        }
#pragma unroll
        for (int mt = 0; mt < 2; mt++)
#pragma unroll
            for (int q = 0; q < 4; q++) Aa[mt][q] = A[mt][q] & 0x7FFF7FFFu;
#pragma unroll
        for (int np = 0; np < 2; np++)
#pragma unroll
            for (int q = 0; q < 4; q++) Ba[np][q] = B2[np][q] & 0x7FFF7FFFu;

#pragma unroll
        for (int mt = 0; mt < 2; mt++)
#pragma unroll
            for (int nt = 0; nt < 4; nt++) {
                const int np = nt >> 1, o = nt & 1;   // o: n8-group within 16
                MMA16816(acc[mt][nt], A[mt],  B2[np][o], B2[np][o + 2]);
                MMA16816(acc[mt][nt], Aa[mt], Ba[np][o], Ba[np][o + 2]);
            }
    }

    // ---- epilogue: y = acc + relu(bias)   (0.5 already folded into W) ----
#pragma unroll
    for (int mt = 0; mt < 2; mt++) {
#pragma unroll
        for (int nt = 0; nt < 4; nt++) {
            const int r0 = bm + wm * 32 + mt * 16 + (lane >> 2);
            const int cl = wn * 32 + nt * 8 + (lane & 3) * 2;
            const float b0 = bias_s[cl], b1 = bias_s[cl + 1];
            float2 v0, v1;
            v0.x = acc[mt][nt][0] + b0;
            v0.y = acc[mt][nt][1] + b1;
            v1.x = acc[mt][nt][2] + b0;
            v1.y = acc[mt][nt][3] + b1;
            *reinterpret_cast<float2*>(out + (size_t)r0 * NDIM + bn + cl) = v0;
            *reinterpret_cast<float2*>(out + (size_t)(r0 + 8) * NDIM + bn + cl) = v1;
        }
    }
}

extern "C" void kernel_launch(void* const* d_in, const int* in_sizes, int n_in,
                              void* d_out, int out_size)
{
    const float* x = (const float*)d_in[0];   // (8192, 256)
    const float* w = (const float*)d_in[1];   // (256, 257)
    float* out = (float*)d_out;               // (8192, 256)

    cudaFuncSetAttribute(skan_mma_kernel,
                         cudaFuncAttributeMaxDynamicSharedMemorySize, DYN_BYTES);

    dim3 grid(NDIM / BN, 8192 / BM);          // (2, 64) = 128 CTAs, one wave
    dim3 block(512);
    skan_mma_kernel<<<grid, block, DYN_BYTES>>>(x, w, out);
}

// round 12
// speedup vs baseline: 1.1723x; 1.1723x over previous
#include <cuda_runtime.h>
#include <cuda_fp16.h>
#include <cstdint>

// y[b,o] = sum_j relu(w[o,j]*x_aug[b,j])
//        = x.(0.5w) + |x|.|0.5w| + relu(w[o,256])   (0.5 folded into W, exact)
// fp16 mma.sync m16n8k16. x streamed GMEM->SMEM as fp32 via cp.async (all 4
// k-chunks issued up front, drained with wait_group), A-frags built by
// LDS.64 + cvt; W resident fp16 via non-trans ldmatrix. 512 thr / 16 warps.

#define BM 128
#define BN 128
#define KDIM 256
#define WSTRIDE 257
#define NDIM 256

#define A_ROW_BYTES 272                    // 64 fp32 + 16B pad (bank de-phase)
#define A_CH_BYTES (128 * A_ROW_BYTES)     // 34816 per k64 chunk
#define B_OFF (4 * A_CH_BYTES)             // 139264
#define B_TILE 16384                       // 128 rows x 64 fp16 (128B rows)
#define DYN_BYTES (B_OFF + 4 * B_TILE + 1024)   // ~205.8 KB

__device__ __forceinline__ uint32_t swz(uint32_t o) { return o ^ ((o >> 3) & 0x70u); }

__device__ __forceinline__ uint32_t smem_u32(const void* p) {
    uint32_t a;
    asm("{ .reg .u64 t; cvta.to.shared.u64 t, %1; cvt.u32.u64 %0, t; }" : "=r"(a) : "l"(p));
    return a;
}

#define LDSM4(r0, r1, r2, r3, addr) \
    asm volatile("ldmatrix.sync.aligned.m8n8.x4.shared.b16 {%0,%1,%2,%3}, [%4];" \
                 : "=r"(r0), "=r"(r1), "=r"(r2), "=r"(r3) : "r"(addr))
#define MMA16816(c, a, b0, b1) \
    asm volatile("mma.sync.aligned.m16n8k16.row.col.f32.f16.f16.f32 " \
                 "{%0,%1,%2,%3}, {%4,%5,%6,%7}, {%8,%9}, {%0,%1,%2,%3};" \
                 : "+f"((c)[0]), "+f"((c)[1]), "+f"((c)[2]), "+f"((c)[3]) \
                 : "r"((a)[0]), "r"((a)[1]), "r"((a)[2]), "r"((a)[3]), "r"(b0), "r"(b1))
#define CP16(dst, src) \
    asm volatile("cp.async.cg.shared.global [%0], [%1], 16;" \
                 :: "r"(dst), "l"(src) : "memory")

__device__ __forceinline__ uint32_t pack_h2(float a, float b) {
    __half2 h = __floats2half2_rn(a, b);
    return *reinterpret_cast<uint32_t*>(&h);
}

__global__ __launch_bounds__(512, 1)
void skan_mma_kernel(const float* __restrict__ x,
                     const float* __restrict__ w,
                     float* __restrict__ out)
{
    extern __shared__ char dynraw[];
    __shared__ float bias_s[BN];

    char* sb = (char*)(((uintptr_t)dynraw + 1023) & ~(uintptr_t)1023);
    const uint32_t sb_u = smem_u32(sb);

    const int tid = threadIdx.x;
    const int lane = tid & 31;
    const int wid = tid >> 5;
    const int bm = blockIdx.y * BM;
    const int bn = blockIdx.x * BN;
    const int wm = wid & 3;     // warp row (4 x 32)
    const int wn = wid >> 2;    // warp col (4 x 32)

    // ---- 1) issue ALL x cp.async copies up front (4 chunks, one group each) ----
    {
        const int row = tid >> 2;          // 0..127
        const int q = tid & 3;             // 64B quarter of the 256B row-chunk
        const float* gsrc = x + (size_t)(bm + row) * KDIM + q * 16;
        const uint32_t sdst = sb_u + (uint32_t)row * A_ROW_BYTES + (uint32_t)q * 64;
#pragma unroll
        for (int u = 0; u < 4; u++) {
#pragma unroll
            for (int i = 0; i < 4; i++)
                CP16(sdst + u * A_CH_BYTES + i * 16, gsrc + u * 64 + i * 4);
            asm volatile("cp.async.commit_group;" ::: "memory");
        }
    }

    // ---- 2) bias + resident B fill (0.5*w as fp16, 4 chunk tiles) ----
    if (tid < BN)
        bias_s[tid] = fmaxf(__ldg(w + (size_t)(bn + tid) * WSTRIDE + 256), 0.0f);
    {
        const int col = lane * 8;                 // 0..248
        char* dstc = sb + B_OFF + (col >> 6) * B_TILE;
        const uint32_t sobase = (uint32_t)((col & 63) * 2);
#pragma unroll
        for (int j = 0; j < 8; j++) {
            const int row = wid + 16 * j;
            const float* wr = w + (size_t)(bn + row) * WSTRIDE + col;
            uint4 st;
            st.x = pack_h2(0.5f * __ldg(wr + 0), 0.5f * __ldg(wr + 1));
            st.y = pack_h2(0.5f * __ldg(wr + 2), 0.5f * __ldg(wr + 3));
            st.z = pack_h2(0.5f * __ldg(wr + 4), 0.5f * __ldg(wr + 5));
            st.w = pack_h2(0.5f * __ldg(wr + 6), 0.5f * __ldg(wr + 7));
            *reinterpret_cast<uint4*>(dstc + swz((uint32_t)(row * 128) + sobase)) = st;
        }
    }

    float acc[2][4][4];
#pragma unroll
    for (int mt = 0; mt < 2; mt++)
#pragma unroll
        for (int nt = 0; nt < 4; nt++)
#pragma unroll
            for (int q = 0; q < 4; q++) acc[mt][nt][q] = 0.0f;

    // ---- 3) per-chunk: drain one cp.async group, barrier, compute 4 kk ----
#pragma unroll
    for (int u = 0; u < 4; u++) {
        if (u == 0)      asm volatile("cp.async.wait_group 3;" ::: "memory");
        else if (u == 1) asm volatile("cp.async.wait_group 2;" ::: "memory");
        else if (u == 2) asm volatile("cp.async.wait_group 1;" ::: "memory");
        else             asm volatile("cp.async.wait_group 0;" ::: "memory");
        __syncthreads();

        const char* Ab = sb + u * A_CH_BYTES;
        const uint32_t Bbase = sb_u + B_OFF + u * B_TILE;

#pragma unroll
        for (int kk = 0; kk < 4; kk++) {
            const int kloc = kk * 16;

            // A fragments: LDS.64 fp32 pairs + cvt-pack to fp16x2
            uint32_t A[2][4], Aa[2][4];
#pragma unroll
            for (int mt = 0; mt < 2; mt++) {
                const int r0 = wm * 32 + mt * 16 + (lane >> 2);
                const char* base = Ab + (size_t)r0 * A_ROW_BYTES
                                 + (kloc + 2 * (lane & 3)) * 4;
                const float2 v0 = *reinterpret_cast<const float2*>(base);
                const float2 v1 = *reinterpret_cast<const float2*>(base + 8 * A_ROW_BYTES);
                const float2 v2 = *reinterpret_cast<const float2*>(base + 32);
                const float2 v3 = *reinterpret_cast<const float2*>(base + 8 * A_ROW_BYTES + 32);
                A[mt][0] = pack_h2(v0.x, v0.y);
                A[mt][1] = pack_h2(v1.x, v1.y);
                A[mt][2] = pack_h2(v2.x, v2.y);
                A[mt][3] = pack_h2(v3.x, v3.y);
            }
            // B: non-trans ldmatrix on [n][k] fp16 tile.
            // matrices: 0 = n0:8 k-lo, 1 = n8:16 k-lo, 2 = n0:8 k-hi, 3 = n8:16 k-hi
            uint32_t B2[2][4], Ba[2][4];
#pragma unroll
            for (int np = 0; np < 2; np++) {
                const int nrow = wn * 32 + np * 16 + (lane & 15);
                const int ncol = kloc + (lane >> 4) * 8;
                const uint32_t addr = Bbase + swz((uint32_t)(nrow * 128 + ncol * 2));
                LDSM4(B2[np][0], B2[np][1], B2[np][2], B2[np][3], addr);
            }
#pragma unroll
            for (int mt = 0; mt < 2; mt++)
#pragma unroll
                for (int q = 0; q < 4; q++) Aa[mt][q] = A[mt][q] & 0x7FFF7FFFu;
#pragma unroll
            for (int np = 0; np < 2; np++)
#pragma unroll
                for (int q = 0; q < 4; q++) Ba[np][q] = B2[np][q] & 0x7FFF7FFFu;

#pragma unroll
            for (int mt = 0; mt < 2; mt++)
#pragma unroll
                for (int nt = 0; nt < 4; nt++) {
                    const int np = nt >> 1, o = nt & 1;   // o: n8-group within 16
                    MMA16816(acc[mt][nt], A[mt],  B2[np][o], B2[np][o + 2]);
                    MMA16816(acc[mt][nt], Aa[mt], Ba[np][o], Ba[np][o + 2]);
                }
        }
    }

    // ---- epilogue: y = acc + relu(bias)   (0.5 already folded into W) ----
#pragma unroll
    for (int mt = 0; mt < 2; mt++) {
#pragma unroll
        for (int nt = 0; nt < 4; nt++) {
            const int r0 = bm + wm * 32 + mt * 16 + (lane >> 2);
            const int cl = wn * 32 + nt * 8 + (lane & 3) * 2;
            const float b0 = bias_s[cl], b1 = bias_s[cl + 1];
            float2 v0, v1;
            v0.x = acc[mt][nt][0] + b0;
            v0.y = acc[mt][nt][1] + b1;
            v1.x = acc[mt][nt][2] + b0;
            v1.y = acc[mt][nt][3] + b1;
            *reinterpret_cast<float2*>(out + (size_t)r0 * NDIM + bn + cl) = v0;
            *reinterpret_cast<float2*>(out + (size_t)(r0 + 8) * NDIM + bn + cl) = v1;
        }
    }
}

extern "C" void kernel_launch(void* const* d_in, const int* in_sizes, int n_in,
                              void* d_out, int out_size)
{
    const float* x = (const float*)d_in[0];   // (8192, 256)
    const float* w = (const float*)d_in[1];   // (256, 257)
    float* out = (float*)d_out;               // (8192, 256)

    cudaFuncSetAttribute(skan_mma_kernel,
                         cudaFuncAttributeMaxDynamicSharedMemorySize, DYN_BYTES);

    dim3 grid(NDIM / BN, 8192 / BM);          // (2, 64) = 128 CTAs, one wave
    dim3 block(512);
    skan_mma_kernel<<<grid, block, DYN_BYTES>>>(x, w, out);
}

// round 13
// speedup vs baseline: 1.6327x; 1.3928x over previous
#include <cuda_runtime.h>
#include <cuda_fp16.h>
#include <cstdint>

// y[b,o] = sum_j relu(w[o,j]*x_aug[b,j])
//        = 0.5*( x.w + |x|.|w| ) + relu(w[o,256])
// fp16 mma.sync m16n8k16; abs on packed fp16x2 regs; both terms -> same fp32 C.
// R6 body (best measured, regs=108) with ONE change: per-mt MMA reorder so each
// acc tile's plain->abs revisit distance is 4 MMAs instead of 1 (HMMA C-latency).

#define BM 128
#define BN 128
#define KDIM 256
#define WSTRIDE 257
#define NDIM 256

#define TILE_BYTES 16384          // 128 rows x 64 fp16 (128B rows)
#define B_OFF (2 * TILE_BYTES)    // after 2 A buffers
#define DYN_BYTES (6 * TILE_BYTES + 1024)

__device__ __forceinline__ uint32_t swz(uint32_t o) { return o ^ ((o >> 3) & 0x70u); }

__device__ __forceinline__ uint32_t smem_u32(const void* p) {
    uint32_t a;
    asm("{ .reg .u64 t; cvta.to.shared.u64 t, %1; cvt.u32.u64 %0, t; }" : "=r"(a) : "l"(p));
    return a;
}

#define LDSM4(r0, r1, r2, r3, addr) \
    asm volatile("ldmatrix.sync.aligned.m8n8.x4.shared.b16 {%0,%1,%2,%3}, [%4];" \
                 : "=r"(r0), "=r"(r1), "=r"(r2), "=r"(r3) : "r"(addr))
#define MMA16816(c, a, b0, b1) \
    asm volatile("mma.sync.aligned.m16n8k16.row.col.f32.f16.f16.f32 " \
                 "{%0,%1,%2,%3}, {%4,%5,%6,%7}, {%8,%9}, {%0,%1,%2,%3};" \
                 : "+f"((c)[0]), "+f"((c)[1]), "+f"((c)[2]), "+f"((c)[3]) \
                 : "r"((a)[0]), "r"((a)[1]), "r"((a)[2]), "r"((a)[3]), "r"(b0), "r"(b1))

// A chunk (128 x 64 fp32): per thread row = tid>>2, 16 consecutive floats
__device__ __forceinline__ void a_load(const float* __restrict__ x, int bm, int u,
                                       int tid, float4* xr) {
    const int row = tid >> 2;
    const int c0 = (tid & 3) * 16;
    const float* p = x + (size_t)(bm + row) * KDIM + u * 64 + c0;
#pragma unroll
    for (int g = 0; g < 4; g++)
        xr[g] = *reinterpret_cast<const float4*>(p + 4 * g);
}

__device__ __forceinline__ uint32_t pack_h2(float a, float b) {
    __half2 h = __floats2half2_rn(a, b);
    return *reinterpret_cast<uint32_t*>(&h);
}

// convert + store one A chunk into swizzled fp16 tile (2 x 16B stores)
__device__ __forceinline__ void a_store(char* sb, int buf, const float4* xr, int tid) {
    char* base = sb + buf * TILE_BYTES;
    const int row = tid >> 2;
    const int c0 = (tid & 3) * 16;
    const uint32_t ob = (uint32_t)(row * 128 + c0 * 2);
#pragma unroll
    for (int s = 0; s < 2; s++) {
        const float4 v0 = xr[2 * s], v1 = xr[2 * s + 1];
        uint4 st;
        st.x = pack_h2(v0.x, v0.y);
        st.y = pack_h2(v0.z, v0.w);
        st.z = pack_h2(v1.x, v1.y);
        st.w = pack_h2(v1.z, v1.w);
        *reinterpret_cast<uint4*>(base + swz(ob + 16 * s)) = st;
    }
}

__global__ __launch_bounds__(512, 1)
void skan_mma_kernel(const float* __restrict__ x,
                     const float* __restrict__ w,
                     float* __restrict__ out)
{
    extern __shared__ char dynraw[];
    __shared__ float bias_s[BN];

    char* sb = (char*)(((uintptr_t)dynraw + 1023) & ~(uintptr_t)1023);
    const uint32_t sb_u = smem_u32(sb);

    const int tid = threadIdx.x;
    const int lane = tid & 31;
    const int wid = tid >> 5;
    const int bm = blockIdx.y * BM;
    const int bn = blockIdx.x * BN;
    const int wm = wid & 3;     // warp row (4 x 32)
    const int wn = wid >> 2;    // warp col (4 x 32)

    if (tid < BN)
        bias_s[tid] = fmaxf(__ldg(w + (size_t)(bn + tid) * WSTRIDE + 256), 0.0f);

    // ---- B fill (once): w[bn..bn+127][0..255] -> 4 resident fp16 chunk tiles ----
#pragma unroll 2
    for (int j = 0; j < 8; j++) {
        const int row = wid + 16 * j;
        const float* wr = w + (size_t)(bn + row) * WSTRIDE;
#pragma unroll
        for (int h = 0; h < 8; h++) {
            const int col = lane + 32 * h;                    // coalesced across lanes
            const __half v = __float2half_rn(__ldg(wr + col));
            char* dst = sb + B_OFF + (col >> 6) * TILE_BYTES +
                        swz((uint32_t)(row * 128 + (col & 63) * 2));
            *reinterpret_cast<__half*>(dst) = v;
        }
    }

    // ---- A chunk 0 ----
    float4 xr[4];
    a_load(x, bm, 0, tid, xr);
    a_store(sb, 0, xr, tid);
    __syncthreads();

    float acc[2][4][4];
#pragma unroll
    for (int mt = 0; mt < 2; mt++)
#pragma unroll
        for (int nt = 0; nt < 4; nt++)
#pragma unroll
            for (int q = 0; q < 4; q++) acc[mt][nt][q] = 0.0f;

    int buf = 0;
#pragma unroll 1
    for (int u = 0; u < 4; u++) {
        if (u < 3) a_load(x, bm, u + 1, tid, xr);

        const uint32_t Abase = sb_u + buf * TILE_BYTES;
        const uint32_t Bbase = sb_u + B_OFF + u * TILE_BYTES;

#pragma unroll
        for (int kk = 0; kk < 4; kk++) {
            uint32_t A[2][4], Aa[2][4];
#pragma unroll
            for (int mt = 0; mt < 2; mt++) {
                const int row = wm * 32 + mt * 16 + (lane & 15);
                const int col = kk * 16 + (lane >> 4) * 8;
                const uint32_t addr = Abase + swz((uint32_t)(row * 128 + col * 2));
                LDSM4(A[mt][0], A[mt][1], A[mt][2], A[mt][3], addr);
            }
            // B: non-trans ldmatrix on [n][k] tile.
            // matrices: 0 = n0:8 k-lo, 1 = n8:16 k-lo, 2 = n0:8 k-hi, 3 = n8:16 k-hi
            uint32_t B2[2][4], Ba[2][4];
#pragma unroll
            for (int np = 0; np < 2; np++) {
                const int nrow = wn * 32 + np * 16 + (lane & 15);
                const int ncol = kk * 16 + (lane >> 4) * 8;
                const uint32_t addr = Bbase + swz((uint32_t)(nrow * 128 + ncol * 2));
                LDSM4(B2[np][0], B2[np][1], B2[np][2], B2[np][3], addr);
            }
#pragma unroll
            for (int mt = 0; mt < 2; mt++)
#pragma unroll
                for (int q = 0; q < 4; q++) Aa[mt][q] = A[mt][q] & 0x7FFF7FFFu;
#pragma unroll
            for (int np = 0; np < 2; np++)
#pragma unroll
                for (int q = 0; q < 4; q++) Ba[np][q] = B2[np][q] & 0x7FFF7FFFu;

            // per-mt: 4 plain MMAs (independent accs), then 4 abs MMAs.
            // Each acc's revisit distance = 4 MMAs (covers HMMA C latency);
            // live-register set identical to the fully-interleaved order.
#pragma unroll
            for (int mt = 0; mt < 2; mt++) {
#pragma unroll
                for (int nt = 0; nt < 4; nt++) {
                    const int np = nt >> 1, o = nt & 1;   // o: n8-group within 16
                    MMA16816(acc[mt][nt], A[mt], B2[np][o], B2[np][o + 2]);
                }
#pragma unroll
                for (int nt = 0; nt < 4; nt++) {
                    const int np = nt >> 1, o = nt & 1;
                    MMA16816(acc[mt][nt], Aa[mt], Ba[np][o], Ba[np][o + 2]);
                }
            }
        }

        if (u < 3) {
            a_store(sb, buf ^ 1, xr, tid);
            __syncthreads();
            buf ^= 1;
        }
    }

    // ---- epilogue: y = 0.5*acc + relu(bias) ----
#pragma unroll
    for (int mt = 0; mt < 2; mt++) {
#pragma unroll
        for (int nt = 0; nt < 4; nt++) {
            const int r0 = bm + wm * 32 + mt * 16 + (lane >> 2);
            const int cl = wn * 32 + nt * 8 + (lane & 3) * 2;
            const float b0 = bias_s[cl], b1 = bias_s[cl + 1];
            float2 v0, v1;
            v0.x = 0.5f * acc[mt][nt][0] + b0;
            v0.y = 0.5f * acc[mt][nt][1] + b1;
            v1.x = 0.5f * acc[mt][nt][2] + b0;
            v1.y = 0.5f * acc[mt][nt][3] + b1;
            *reinterpret_cast<float2*>(out + (size_t)r0 * NDIM + bn + cl) = v0;
            *reinterpret_cast<float2*>(out + (size_t)(r0 + 8) * NDIM + bn + cl) = v1;
        }
    }
}

extern "C" void kernel_launch(void* const* d_in, const int* in_sizes, int n_in,
                              void* d_out, int out_size)
{
    const float* x = (const float*)d_in[0];   // (8192, 256)
    const float* w = (const float*)d_in[1];   // (256, 257)
    float* out = (float*)d_out;               // (8192, 256)

    cudaFuncSetAttribute(skan_mma_kernel,
                         cudaFuncAttributeMaxDynamicSharedMemorySize, DYN_BYTES);

    dim3 grid(NDIM / BN, 8192 / BM);          // (2, 64) = 128 CTAs, one wave
    dim3 block(512);
    skan_mma_kernel<<<grid, block, DYN_BYTES>>>(x, w, out);
}